// round 3
// baseline (speedup 1.0000x reference)
#include <cuda_runtime.h>
#include <cuda_bf16.h>
#include <stdint.h>

#define BB      8192
#define LBITS   128
#define NP      4096
#define MARGIN  64
#define NBLK    256

// ---------------- device scratch (static allocation: allowed) ----------------
__device__ unsigned long long g_pos_sum;
__device__ unsigned long long g_neg_sum;
__device__ double             g_quant_part[NBLK];
__device__ int                g_colsum[LBITS];
__device__ uint4              g_bits4[BB];     // 128 bits per row (16B aligned)
__device__ int                g_odd_flag;      // 1 if positives buffer is int32

// ---------------- kernel 0: zero accumulators --------------------------------
__global__ void zero_kernel() {
    int t = threadIdx.x;   // 256 threads
    if (t == 0) { g_pos_sum = 0ull; g_neg_sum = 0ull; g_odd_flag = 0; }
    if (t < LBITS) g_colsum[t] = 0;
    g_quant_part[t] = 0.0;
}

// ---------------- kernel 0b: detect positives dtype layout -------------------
// int64 layout: odd 32-bit words of the first 32KB are all zero (values<8192).
// int32 layout: odd words are random indices -> some nonzero.
// Reads only the first 32KB, which is valid under BOTH layouts.
__global__ void detect_kernel(const int* __restrict__ pos32) {
    int i = blockIdx.x * blockDim.x + threadIdx.x;   // 0..4095
    if (i < NP && pos32[2 * i + 1] != 0) atomicOr(&g_odd_flag, 1);
}

// helper: fetch pair p under either layout
__device__ __forceinline__ void get_pair(const void* pos, int is32, int p,
                                         int& q, int& d) {
    if (is32) {
        const int* p32 = (const int*)pos;
        q = p32[2 * p] & (BB - 1);
        d = p32[2 * p + 1] & (BB - 1);
    } else {
        const long long* p64 = (const long long*)pos;
        q = (int)p64[2 * p] & (BB - 1);
        d = (int)p64[2 * p + 1] & (BB - 1);
    }
}

// ---------------- kernel 1: pack sign bits + quant loss + column sums --------
// blockDim = 128 (one thread per bit-column), grid = 256 blocks x 32 rows each
__global__ void pack_stats_kernel(const float* __restrict__ bh,
                                  const float* __restrict__ ch) {
    int tid  = threadIdx.x;          // column 0..127
    int warp = tid >> 5;
    int lane = tid & 31;
    int colacc   = 0;
    float quacc  = 0.f;
    int row0 = blockIdx.x * 32;
    #pragma unroll 4
    for (int i = 0; i < 32; ++i) {
        int row = row0 + i;
        float x = bh[row * LBITS + tid];
        unsigned m = __ballot_sync(0xffffffffu, x < 0.f);
        if (lane == 0) ((unsigned*)&g_bits4[row])[warp] = m;
        colacc += (x < 0.f) ? -1 : 1;                 // sign(x)
        float c = ch[row * LBITS + tid];
        quacc += fabsf(fabsf(c) - 1.f);
    }
    atomicAdd(&g_colsum[tid], colacc);
    __shared__ double s[128];
    s[tid] = (double)quacc;
    __syncthreads();
    for (int off = 64; off > 0; off >>= 1) {
        if (tid < off) s[tid] += s[tid + off];
        __syncthreads();
    }
    if (tid == 0) g_quant_part[blockIdx.x] = s[0];   // deterministic partials
}

// ---------------- kernel 2: positive pair loss (popcount dots) ---------------
__global__ void pos_kernel(const void* __restrict__ pos) {
    int p = blockIdx.x * blockDim.x + threadIdx.x;
    int is32 = g_odd_flag;
    unsigned term = 0;
    if (p < NP) {
        int q, d;
        get_pair(pos, is32, p, q, d);
        uint4 a = g_bits4[q];
        uint4 b = g_bits4[d];
        int D = __popc(a.x ^ b.x) + __popc(a.y ^ b.y)
              + __popc(a.z ^ b.z) + __popc(a.w ^ b.w);
        int dot  = LBITS - 2 * D;
        int diff = MARGIN - dot;
        if (diff > 0) term = (unsigned)(diff * diff);
    }
    #pragma unroll
    for (int off = 16; off; off >>= 1)
        term += __shfl_down_sync(0xffffffffu, term, off);
    if ((threadIdx.x & 31) == 0 && term)
        atomicAdd(&g_pos_sum, (unsigned long long)term);
}

// ---------------- kernel 3: negative loss ------------------------------------
// Selection (csum <= NP) is provably confined to flat entries of rows 0 and 1:
// those two rows contain >= 2*(BB-1) - 2*NP = 8190 >= 4096 candidates.
// One block, 1024 threads, 16 flat entries per thread, block scan for prefix.
__global__ void __launch_bounds__(1024, 1) neg_kernel(const void* __restrict__ pos) {
    __shared__ unsigned char flags[2 * BB];   // 16 KB
    __shared__ int scan[1024];
    int tid = threadIdx.x;
    int is32 = g_odd_flag;

    for (int i = tid; i < 2 * BB; i += 1024) flags[i] = 0;
    __syncthreads();
    for (int p = tid; p < NP; p += 1024) {
        int q, d;
        get_pair(pos, is32, p, q, d);
        if (q < 2) flags[q * BB + d] = 1;
        if (d < 2) flags[d * BB + q] = 1;
    }
    if (tid == 0) { flags[0] = 1; flags[BB + 1] = 1; }  // diagonal (0,0),(1,1)
    __syncthreads();

    uint4 r0 = g_bits4[0];
    uint4 r1 = g_bits4[1];

    int gval[16];
    unsigned candm = 0;
    int cnt = 0;
    int base = tid * 16;
    #pragma unroll
    for (int i = 0; i < 16; ++i) {
        int e   = base + i;
        int row = e >> 13;
        int col = e & (BB - 1);
        uint4 r = row ? r1 : r0;
        uint4 c = g_bits4[col];
        int D = __popc(r.x ^ c.x) + __popc(r.y ^ c.y)
              + __popc(r.z ^ c.z) + __popc(r.w ^ c.w);
        gval[i] = LBITS - 2 * D;
        if (!flags[e]) { candm |= (1u << i); cnt++; }
    }
    scan[tid] = cnt;
    __syncthreads();
    // Hillis-Steele inclusive scan over 1024 counts
    for (int off = 1; off < 1024; off <<= 1) {
        int v = (tid >= off) ? scan[tid - off] : 0;
        __syncthreads();
        scan[tid] += v;
        __syncthreads();
    }
    int run = scan[tid] - cnt;   // exclusive prefix of candidates
    unsigned acc = 0;
    #pragma unroll
    for (int i = 0; i < 16; ++i) {
        if (candm & (1u << i)) {
            if (run < NP) {
                int v = gval[i] + MARGIN;
                if (v > 0) acc += (unsigned)(v * v);
            }
            run++;
        }
    }
    #pragma unroll
    for (int off = 16; off; off >>= 1)
        acc += __shfl_down_sync(0xffffffffu, acc, off);
    if ((tid & 31) == 0 && acc)
        atomicAdd(&g_neg_sum, (unsigned long long)acc);
}

// ---------------- kernel 4: combine ------------------------------------------
__global__ void final_kernel(float* __restrict__ out) {
    // num_neg = min(total_candidates(~67M), NP) = NP always for this shape
    double sim = (double)(g_pos_sum + g_neg_sum) / (double)(NP + NP);
    double qs = 0.0;
    for (int i = 0; i < NBLK; ++i) qs += g_quant_part[i];
    double quant = qs / ((double)BB * (double)LBITS);
    double bal = 0.0;
    #pragma unroll 8
    for (int c = 0; c < LBITS; ++c) {
        double m = (double)g_colsum[c] / (double)BB;
        bal += m * m;
    }
    out[0] = (float)(1.0 * sim + 0.5 * quant + 0.1 * bal);
}

// ---------------- launch ------------------------------------------------------
extern "C" void kernel_launch(void* const* d_in, const int* in_sizes, int n_in,
                              void* d_out, int out_size) {
    const float* bh  = (const float*)d_in[0];
    const float* ch  = (const float*)d_in[1];
    const void*  pos = (const void*)d_in[2];

    zero_kernel<<<1, 256>>>();
    detect_kernel<<<(NP + 255) / 256, 256>>>((const int*)pos);
    pack_stats_kernel<<<NBLK, 128>>>(bh, ch);
    pos_kernel<<<(NP + 255) / 256, 256>>>(pos);
    neg_kernel<<<1, 1024>>>(pos);
    final_kernel<<<1, 1>>>((float*)d_out);
}

// round 5
// speedup vs baseline: 1.3024x; 1.3024x over previous
#include <cuda_runtime.h>
#include <cuda_bf16.h>
#include <stdint.h>

#define BB       8192
#define LBITS    128
#define NP       4096
#define MARGIN   64
#define NBLOCKS  128
#define NT       512
#define POSBLKS  8          // blocks 1..8 handle positives
#define DONECNT  9          // blocks 0..8 participate in done counter

// ---------------- device scratch (static, zero-init at module load) ----------
__device__ uint4        g_bits4[BB];               // packed sign bits per row
__device__ double       g_quant_part[NBLOCKS];     // per-block quant partials
__device__ int          g_col_part[NBLOCKS][LBITS];
__device__ unsigned     g_pos_part[POSBLKS];
__device__ unsigned     g_neg_part;
__device__ unsigned     g_bar;                     // monotonic barrier ticket
__device__ unsigned     g_done;                    // monotonic done ticket

__global__ void __launch_bounds__(NT, 1)
fused_kernel(const float* __restrict__ bh,
             const float* __restrict__ ch,
             const void*  __restrict__ pos,
             float*       __restrict__ out)
{
    __shared__ unsigned char flags[2 * BB];   // 16 KB (neg block only)
    __shared__ int    scan[NT];
    __shared__ int    s_col[LBITS];
    __shared__ float  s_q[NT / 32];
    __shared__ double s_bal[LBITS];
    __shared__ int    s_final;

    const int tid  = threadIdx.x;
    const int warp = tid >> 5;
    const int lane = tid & 31;
    const int bx   = blockIdx.x;

    // ================= PHASE 1: pack bits + quant + column sums ==============
    if (tid < LBITS) s_col[tid] = 0;
    if (tid == 0)    s_final = 0;
    __syncthreads();

    float quacc = 0.f;
    int   ca0 = 0, ca1 = 0, ca2 = 0, ca3 = 0;
    #pragma unroll
    for (int it = 0; it < 4; ++it) {
        int r = bx * 64 + warp * 4 + it;          // 64 rows per block
        float4 x = ((const float4*)bh)[r * 32 + lane];
        unsigned b0 = __ballot_sync(0xffffffffu, x.x < 0.f);
        unsigned b1 = __ballot_sync(0xffffffffu, x.y < 0.f);
        unsigned b2 = __ballot_sync(0xffffffffu, x.z < 0.f);
        unsigned b3 = __ballot_sync(0xffffffffu, x.w < 0.f);
        if (lane == 0) g_bits4[r] = make_uint4(b0, b1, b2, b3);
        ca0 += (x.x < 0.f) ? -1 : 1;
        ca1 += (x.y < 0.f) ? -1 : 1;
        ca2 += (x.z < 0.f) ? -1 : 1;
        ca3 += (x.w < 0.f) ? -1 : 1;
        float4 c = ((const float4*)ch)[r * 32 + lane];
        quacc += fabsf(fabsf(c.x) - 1.f) + fabsf(fabsf(c.y) - 1.f)
               + fabsf(fabsf(c.z) - 1.f) + fabsf(fabsf(c.w) - 1.f);
    }
    // permuted column ownership: lane l owns columns 4l..4l+3 (consistent
    // permutation across all rows -> dots, colsums, sum(m^2) all invariant)
    atomicAdd(&s_col[4 * lane + 0], ca0);
    atomicAdd(&s_col[4 * lane + 1], ca1);
    atomicAdd(&s_col[4 * lane + 2], ca2);
    atomicAdd(&s_col[4 * lane + 3], ca3);
    #pragma unroll
    for (int off = 16; off; off >>= 1)
        quacc += __shfl_down_sync(0xffffffffu, quacc, off);
    if (lane == 0) s_q[warp] = quacc;
    __syncthreads();
    if (tid < LBITS) g_col_part[bx][tid] = s_col[tid];
    if (tid == 0) {
        double qq = 0.0;
        #pragma unroll
        for (int i = 0; i < NT / 32; ++i) qq += (double)s_q[i];
        g_quant_part[bx] = qq;
    }
    __threadfence();

    // ================= monotonic ticket barrier (no resets) ==================
    if (tid == 0) {
        unsigned t = atomicAdd(&g_bar, 1u);
        unsigned target = (t / NBLOCKS + 1u) * NBLOCKS;
        while (*(volatile unsigned*)&g_bar < target) { }
    }
    __syncthreads();
    __threadfence();   // acquire: g_bits4 / partials from all blocks visible

    // ================= PHASE 2 ==============================================
    if (bx < DONECNT) {
        // ---- local dtype detection (int64 vs int32 positives) ----
        const int* p32 = (const int*)pos;
        int any = 0;
        for (int i = tid; i < NP; i += NT) any |= (p32[2 * i + 1] != 0);
        const int is32 = __syncthreads_or(any);

        if (bx >= 1) {
            // -------- positive pair loss: 512 pairs per block --------
            int p = (bx - 1) * NT + tid;
            int q, d;
            if (is32) { q = p32[2 * p] & (BB - 1); d = p32[2 * p + 1] & (BB - 1); }
            else      { q = p32[4 * p] & (BB - 1); d = p32[4 * p + 2] & (BB - 1); }
            uint4 a = g_bits4[q];
            uint4 b = g_bits4[d];
            int D = __popc(a.x ^ b.x) + __popc(a.y ^ b.y)
                  + __popc(a.z ^ b.z) + __popc(a.w ^ b.w);
            int diff = MARGIN - (LBITS - 2 * D);
            unsigned term = (diff > 0) ? (unsigned)(diff * diff) : 0u;
            #pragma unroll
            for (int off = 16; off; off >>= 1)
                term += __shfl_down_sync(0xffffffffu, term, off);
            if (lane == 0) scan[warp] = (int)term;
            __syncthreads();
            if (tid == 0) {
                unsigned bs = 0;
                #pragma unroll
                for (int w = 0; w < NT / 32; ++w) bs += (unsigned)scan[w];
                g_pos_part[bx - 1] = bs;
            }
        } else {
            // -------- negative loss: confined to rows 0,1 (proof: those two
            // rows hold >= 2*(BB-1) - 2*NP = 8190 >= NP candidates) --------
            for (int i = tid; i < (2 * BB) / 4; i += NT)
                ((int*)flags)[i] = 0;
            __syncthreads();
            for (int p = tid; p < NP; p += NT) {
                int q, d;
                if (is32) { q = p32[2 * p] & (BB - 1); d = p32[2 * p + 1] & (BB - 1); }
                else      { q = p32[4 * p] & (BB - 1); d = p32[4 * p + 2] & (BB - 1); }
                if (q < 2) flags[q * BB + d] = 1;
                if (d < 2) flags[d * BB + q] = 1;
            }
            if (tid == 0) { flags[0] = 1; flags[BB + 1] = 1; }  // diag (0,0),(1,1)
            __syncthreads();

            const int base = tid * 32;
            int cnt = 0;
            #pragma unroll
            for (int i = 0; i < 32; ++i) cnt += flags[base + i] ? 0 : 1;
            scan[tid] = cnt;
            __syncthreads();
            for (int off = 1; off < NT; off <<= 1) {
                int v = (tid >= off) ? scan[tid - off] : 0;
                __syncthreads();
                scan[tid] += v;
                __syncthreads();
            }
            int run = scan[tid] - cnt;   // exclusive prefix of candidates
            uint4 r0 = g_bits4[0];
            uint4 r1 = g_bits4[1];
            unsigned acc = 0;
            #pragma unroll
            for (int i = 0; i < 32; ++i) {
                int e = base + i;
                if (!flags[e]) {
                    if (run < NP) {
                        int col = e & (BB - 1);
                        uint4 rr = (e >> 13) ? r1 : r0;
                        uint4 c  = g_bits4[col];
                        int D = __popc(rr.x ^ c.x) + __popc(rr.y ^ c.y)
                              + __popc(rr.z ^ c.z) + __popc(rr.w ^ c.w);
                        int v = (LBITS - 2 * D) + MARGIN;
                        if (v > 0) acc += (unsigned)(v * v);
                    }
                    run++;
                }
            }
            #pragma unroll
            for (int off = 16; off; off >>= 1)
                acc += __shfl_down_sync(0xffffffffu, acc, off);
            if (lane == 0) scan[warp] = (int)acc;
            __syncthreads();
            if (tid == 0) {
                unsigned bs = 0;
                #pragma unroll
                for (int w = 0; w < NT / 32; ++w) bs += (unsigned)scan[w];
                g_neg_part = bs;
            }
        }

        // ============== done counter: last of 9 blocks does final ==========
        __threadfence();
        __syncthreads();
        if (tid == 0) {
            unsigned t2 = atomicAdd(&g_done, 1u);
            if (t2 % DONECNT == (DONECNT - 1)) s_final = 1;
        }
        __syncthreads();

        if (s_final) {
            __threadfence();   // acquire partials from sibling blocks
            // bit-balance: thread c sums its column over all 128 blocks
            if (tid < LBITS) {
                int cs = 0;
                #pragma unroll 8
                for (int b = 0; b < NBLOCKS; ++b) cs += g_col_part[b][tid];
                double m = (double)cs / (double)BB;
                s_bal[tid] = m * m;
            }
            __syncthreads();
            if (tid == 0) {
                double bal = 0.0, qs = 0.0;
                #pragma unroll 8
                for (int c = 0; c < LBITS; ++c) bal += s_bal[c];
                #pragma unroll 8
                for (int b = 0; b < NBLOCKS; ++b) qs += g_quant_part[b];
                unsigned long long psum = (unsigned long long)g_neg_part;
                #pragma unroll
                for (int b = 0; b < POSBLKS; ++b) psum += g_pos_part[b];
                // num_neg = min(~67M, NP) = NP always for this shape
                double sim   = (double)psum / (double)(NP + NP);
                double quant = qs / ((double)BB * (double)LBITS);
                out[0] = (float)(sim + 0.5 * quant + 0.1 * bal);
            }
        }
    }
}

// ---------------- launch ------------------------------------------------------
extern "C" void kernel_launch(void* const* d_in, const int* in_sizes, int n_in,
                              void* d_out, int out_size) {
    const float* bh  = (const float*)d_in[0];
    const float* ch  = (const float*)d_in[1];
    const void*  pos = (const void*)d_in[2];
    fused_kernel<<<NBLOCKS, NT>>>(bh, ch, pos, (float*)d_out);
}

// round 6
// speedup vs baseline: 1.6564x; 1.2718x over previous
#include <cuda_runtime.h>
#include <cuda_bf16.h>
#include <stdint.h>

#define BB       8192
#define LBITS    128
#define NP       4096
#define MARGIN   64
#define NPACK    128            // phase-1 blocks
#define NWAIT    5              // blocks 0..4: 0 = neg, 1..4 = pos
#define GRID     (NPACK + NWAIT)
#define NT       1024

// ---------------- device scratch (static, zero-init at module load) ----------
__device__ uint4        g_bits4[BB];              // packed sign bits per row
__device__ double       g_quant_part[NPACK];
__device__ int          g_col_part[NPACK][LBITS];
__device__ unsigned     g_pos_part[NWAIT - 1];
__device__ unsigned     g_neg_part;
__device__ unsigned     g_bar;                    // monotonic barrier ticket
__device__ unsigned     g_done;                   // monotonic done ticket

__global__ void __launch_bounds__(NT, 1)
fused_kernel(const float* __restrict__ bh,
             const float* __restrict__ ch,
             const void*  __restrict__ pos,
             float*       __restrict__ out)
{
    __shared__ unsigned char flags[2 * BB];   // 16 KB (neg block only)
    __shared__ int    scan[NT];
    __shared__ int    s_col[LBITS];
    __shared__ float  s_q[NT / 32];
    __shared__ double s_bal[LBITS];
    __shared__ int    s_final;

    const int tid  = threadIdx.x;
    const int warp = tid >> 5;
    const int lane = tid & 31;
    const int bx   = blockIdx.x;

    if (tid == 0) s_final = 0;

    int my_q = 0, my_d = 0;      // pos-block pair prefetch
    int cnt = 0;                 // neg-block candidate count

    if (bx >= NWAIT) {
        // ================= PHASE 1: pack + quant + colsums (128 blocks) ======
        const int pb = bx - NWAIT;
        if (tid < LBITS) s_col[tid] = 0;
        __syncthreads();

        float quacc = 0.f;
        int ca0 = 0, ca1 = 0, ca2 = 0, ca3 = 0;
        #pragma unroll
        for (int it = 0; it < 2; ++it) {
            int r = pb * 64 + warp * 2 + it;       // 64 rows per block
            float4 x = ((const float4*)bh)[r * 32 + lane];
            float4 c = ((const float4*)ch)[r * 32 + lane];
            unsigned b0 = __ballot_sync(0xffffffffu, x.x < 0.f);
            unsigned b1 = __ballot_sync(0xffffffffu, x.y < 0.f);
            unsigned b2 = __ballot_sync(0xffffffffu, x.z < 0.f);
            unsigned b3 = __ballot_sync(0xffffffffu, x.w < 0.f);
            if (lane == 0) g_bits4[r] = make_uint4(b0, b1, b2, b3);
            ca0 += (x.x < 0.f) ? -1 : 1;
            ca1 += (x.y < 0.f) ? -1 : 1;
            ca2 += (x.z < 0.f) ? -1 : 1;
            ca3 += (x.w < 0.f) ? -1 : 1;
            quacc += fabsf(fabsf(c.x) - 1.f) + fabsf(fabsf(c.y) - 1.f)
                   + fabsf(fabsf(c.z) - 1.f) + fabsf(fabsf(c.w) - 1.f);
        }
        // consistent column permutation across all rows: lane l owns 4l..4l+3
        // (XOR dots, colsums, sum(m^2) are permutation-invariant)
        atomicAdd(&s_col[4 * lane + 0], ca0);
        atomicAdd(&s_col[4 * lane + 1], ca1);
        atomicAdd(&s_col[4 * lane + 2], ca2);
        atomicAdd(&s_col[4 * lane + 3], ca3);
        #pragma unroll
        for (int off = 16; off; off >>= 1)
            quacc += __shfl_down_sync(0xffffffffu, quacc, off);
        if (lane == 0) s_q[warp] = quacc;
        __syncthreads();
        if (tid < LBITS) g_col_part[pb][tid] = s_col[tid];
        if (tid == 0) {
            double qq = 0.0;
            #pragma unroll
            for (int i = 0; i < NT / 32; ++i) qq += (double)s_q[i];
            g_quant_part[pb] = qq;
        }
        // release + arrive; pack blocks exit without spinning
        __threadfence();
        __syncthreads();
        if (tid == 0) atomicAdd(&g_bar, 1u);
        return;
    }

    // ================= PHASE-2 blocks: prep BEFORE the barrier ===============
    const int* p32 = (const int*)pos;
    // dtype detect: int64 little-endian with values<8192 -> odd words all zero
    int any = 0;
    for (int i = tid; i < NP; i += NT) any |= (p32[2 * i + 1] != 0);
    const int is32 = __syncthreads_or(any);

    if (bx >= 1) {
        // pos blocks: prefetch this thread's pair (1024 pairs per block)
        int p = (bx - 1) * NT + tid;
        if (is32) { my_q = p32[2 * p] & (BB - 1); my_d = p32[2 * p + 1] & (BB - 1); }
        else      { my_q = p32[4 * p] & (BB - 1); my_d = p32[4 * p + 2] & (BB - 1); }
    } else {
        // neg block: build flags + block scan (depends only on positives)
        // selection is provably confined to rows 0,1: those rows hold
        // >= 2*(BB-1) - 2*NP = 8190 >= NP candidates.
        for (int i = tid; i < (2 * BB) / 4; i += NT) ((int*)flags)[i] = 0;
        __syncthreads();
        for (int p = tid; p < NP; p += NT) {
            int q, d;
            if (is32) { q = p32[2 * p] & (BB - 1); d = p32[2 * p + 1] & (BB - 1); }
            else      { q = p32[4 * p] & (BB - 1); d = p32[4 * p + 2] & (BB - 1); }
            if (q < 2) flags[q * BB + d] = 1;
            if (d < 2) flags[d * BB + q] = 1;
        }
        if (tid == 0) { flags[0] = 1; flags[BB + 1] = 1; }  // diag (0,0),(1,1)
        __syncthreads();
        const int base = tid * 16;
        #pragma unroll
        for (int i = 0; i < 16; ++i) cnt += flags[base + i] ? 0 : 1;
        scan[tid] = cnt;
        __syncthreads();
        for (int off = 1; off < NT; off <<= 1) {     // Hillis-Steele, 10 steps
            int v = (tid >= off) ? scan[tid - off] : 0;
            __syncthreads();
            scan[tid] += v;
            __syncthreads();
        }
    }

    // ================= monotonic ticket barrier (waiters only) ===============
    if (tid == 0) {
        unsigned t = atomicAdd(&g_bar, 1u);
        unsigned target = (t / GRID + 1u) * GRID;
        while (*(volatile unsigned*)&g_bar < target) { }
    }
    __syncthreads();
    __threadfence();   // acquire: g_bits4 + phase-1 partials visible

    // ================= PHASE 2: popcount work =================================
    if (bx >= 1) {
        uint4 a = g_bits4[my_q];
        uint4 b = g_bits4[my_d];
        int D = __popc(a.x ^ b.x) + __popc(a.y ^ b.y)
              + __popc(a.z ^ b.z) + __popc(a.w ^ b.w);
        int diff = MARGIN - (LBITS - 2 * D);
        unsigned term = (diff > 0) ? (unsigned)(diff * diff) : 0u;
        #pragma unroll
        for (int off = 16; off; off >>= 1)
            term += __shfl_down_sync(0xffffffffu, term, off);
        if (lane == 0) s_q[warp] = __uint_as_float(term);
        __syncthreads();
        if (tid == 0) {
            unsigned bs = 0;
            #pragma unroll
            for (int w = 0; w < NT / 32; ++w) bs += __float_as_uint(s_q[w]);
            g_pos_part[bx - 1] = bs;
        }
    } else {
        int run = scan[tid] - cnt;   // exclusive prefix of candidates
        uint4 r0 = g_bits4[0];
        uint4 r1 = g_bits4[1];
        unsigned acc = 0;
        const int base = tid * 16;
        #pragma unroll
        for (int i = 0; i < 16; ++i) {
            int e = base + i;
            if (!flags[e]) {
                if (run < NP) {
                    int col = e & (BB - 1);
                    uint4 rr = (e >> 13) ? r1 : r0;
                    uint4 c  = g_bits4[col];
                    int D = __popc(rr.x ^ c.x) + __popc(rr.y ^ c.y)
                          + __popc(rr.z ^ c.z) + __popc(rr.w ^ c.w);
                    int v = (LBITS - 2 * D) + MARGIN;
                    if (v > 0) acc += (unsigned)(v * v);
                }
                run++;
            }
        }
        #pragma unroll
        for (int off = 16; off; off >>= 1)
            acc += __shfl_down_sync(0xffffffffu, acc, off);
        if (lane == 0) s_q[warp] = __uint_as_float(acc);
        __syncthreads();
        if (tid == 0) {
            unsigned bs = 0;
            #pragma unroll
            for (int w = 0; w < NT / 32; ++w) bs += __float_as_uint(s_q[w]);
            g_neg_part = bs;
        }
    }

    // ================= done counter: last of 5 blocks combines ================
    __threadfence();
    __syncthreads();
    if (tid == 0) {
        unsigned t2 = atomicAdd(&g_done, 1u);
        if (t2 % NWAIT == (NWAIT - 1)) s_final = 1;
    }
    __syncthreads();

    if (s_final) {
        __threadfence();   // acquire sibling partials
        if (tid < LBITS) {
            int cs = 0;
            #pragma unroll 8
            for (int b = 0; b < NPACK; ++b) cs += g_col_part[b][tid];
            double m = (double)cs / (double)BB;
            s_bal[tid] = m * m;
        }
        __syncthreads();
        if (tid == 0) {
            double bal = 0.0, qs = 0.0;
            #pragma unroll 8
            for (int c = 0; c < LBITS; ++c) bal += s_bal[c];
            #pragma unroll 8
            for (int b = 0; b < NPACK; ++b) qs += g_quant_part[b];
            unsigned long long psum = (unsigned long long)g_neg_part;
            #pragma unroll
            for (int b = 0; b < NWAIT - 1; ++b) psum += g_pos_part[b];
            // num_neg = min(~67M, NP) = NP always for this shape
            double sim   = (double)psum / (double)(NP + NP);
            double quant = qs / ((double)BB * (double)LBITS);
            out[0] = (float)(sim + 0.5 * quant + 0.1 * bal);
        }
    }
}

// ---------------- launch ------------------------------------------------------
extern "C" void kernel_launch(void* const* d_in, const int* in_sizes, int n_in,
                              void* d_out, int out_size) {
    const float* bh  = (const float*)d_in[0];
    const float* ch  = (const float*)d_in[1];
    const void*  pos = (const void*)d_in[2];
    fused_kernel<<<GRID, NT>>>(bh, ch, pos, (float*)d_out);
}

// round 7
// speedup vs baseline: 2.0391x; 1.2311x over previous
#include <cuda_runtime.h>
#include <cuda_bf16.h>
#include <stdint.h>

#define BB      8192
#define LBITS   128
#define NP      4096
#define MARGIN  64
#define NPOSB   16                 // blocks 1..16: positive pairs
#define NPACK   128                // blocks 17..144: streaming/pack
#define PACK0   (1 + NPOSB)
#define GRID    (1 + NPOSB + NPACK)   // 145 blocks, single wave
#define NT      1024

// ---------------- device scratch (static, zero-init at load) -----------------
__device__ double       g_quant_part[NPACK];
__device__ int          g_col_part[NPACK][LBITS];
__device__ unsigned     g_pos_part[NPOSB];
__device__ unsigned     g_neg_part;
__device__ uint4        g_dots4[BB / 4];   // per row: (dot0+128)|(dot1+128)<<16
__device__ unsigned     g_dots_done;       // monotonic: +1 per pack block
__device__ unsigned     g_epoch;           // monotonic: neg-block replay ticket
__device__ unsigned     g_done;            // monotonic: all-blocks done ticket

__global__ void __launch_bounds__(NT, 1)
fused_kernel(const float* __restrict__ bh,
             const float* __restrict__ ch,
             const void*  __restrict__ pos,
             float*       __restrict__ out)
{
    __shared__ unsigned char flags[2 * BB];   // 16 KB (neg block only)
    __shared__ int    scan[NT];
    __shared__ int    s_col[LBITS];
    __shared__ float  s_q[NT / 32];
    __shared__ double s_d[LBITS];
    __shared__ int    s_final;
    __shared__ unsigned s_epoch;

    const int tid  = threadIdx.x;
    const int warp = tid >> 5;
    const int lane = tid & 31;
    const int bx   = blockIdx.x;

    if (tid == 0) s_final = 0;

    if (bx >= PACK0) {
        // ========== PACK blocks: stream bh+ch, colsums, quant, dots vs r0/r1 =
        const int pb = bx - PACK0;
        if (tid < LBITS) s_col[tid] = 0;
        __syncthreads();

        // rows 0 and 1 packed bits (identical in every warp; 1KB L2 broadcast)
        float4 r0f = ((const float4*)bh)[lane];
        float4 r1f = ((const float4*)bh)[32 + lane];
        unsigned r00 = __ballot_sync(0xffffffffu, r0f.x < 0.f);
        unsigned r01 = __ballot_sync(0xffffffffu, r0f.y < 0.f);
        unsigned r02 = __ballot_sync(0xffffffffu, r0f.z < 0.f);
        unsigned r03 = __ballot_sync(0xffffffffu, r0f.w < 0.f);
        unsigned r10 = __ballot_sync(0xffffffffu, r1f.x < 0.f);
        unsigned r11 = __ballot_sync(0xffffffffu, r1f.y < 0.f);
        unsigned r12 = __ballot_sync(0xffffffffu, r1f.z < 0.f);
        unsigned r13 = __ballot_sync(0xffffffffu, r1f.w < 0.f);

        float quacc = 0.f;
        int ca0 = 0, ca1 = 0, ca2 = 0, ca3 = 0;
        #pragma unroll
        for (int it = 0; it < 2; ++it) {
            int r = pb * 64 + warp * 2 + it;       // 64 rows per block
            float4 x = ((const float4*)bh)[r * 32 + lane];
            float4 c = ((const float4*)ch)[r * 32 + lane];
            unsigned b0 = __ballot_sync(0xffffffffu, x.x < 0.f);
            unsigned b1 = __ballot_sync(0xffffffffu, x.y < 0.f);
            unsigned b2 = __ballot_sync(0xffffffffu, x.z < 0.f);
            unsigned b3 = __ballot_sync(0xffffffffu, x.w < 0.f);
            // dots vs rows 0,1 (lane->column permutation consistent: invariant)
            int D0 = __popc(b0 ^ r00) + __popc(b1 ^ r01)
                   + __popc(b2 ^ r02) + __popc(b3 ^ r03);
            int D1 = __popc(b0 ^ r10) + __popc(b1 ^ r11)
                   + __popc(b2 ^ r12) + __popc(b3 ^ r13);
            if (lane == 0)
                ((unsigned*)g_dots4)[r] =
                    (unsigned)(LBITS - 2 * D0 + 128)
                  | ((unsigned)(LBITS - 2 * D1 + 128) << 16);
            ca0 += (x.x < 0.f) ? -1 : 1;
            ca1 += (x.y < 0.f) ? -1 : 1;
            ca2 += (x.z < 0.f) ? -1 : 1;
            ca3 += (x.w < 0.f) ? -1 : 1;
            quacc += fabsf(fabsf(c.x) - 1.f) + fabsf(fabsf(c.y) - 1.f)
                   + fabsf(fabsf(c.z) - 1.f) + fabsf(fabsf(c.w) - 1.f);
        }
        atomicAdd(&s_col[4 * lane + 0], ca0);
        atomicAdd(&s_col[4 * lane + 1], ca1);
        atomicAdd(&s_col[4 * lane + 2], ca2);
        atomicAdd(&s_col[4 * lane + 3], ca3);
        #pragma unroll
        for (int off = 16; off; off >>= 1)
            quacc += __shfl_down_sync(0xffffffffu, quacc, off);
        if (lane == 0) s_q[warp] = quacc;
        __syncthreads();
        if (tid < LBITS) g_col_part[pb][tid] = s_col[tid];
        if (tid == 0) {
            double qq = 0.0;
            #pragma unroll
            for (int i = 0; i < NT / 32; ++i) qq += (double)s_q[i];
            g_quant_part[pb] = qq;
        }
        __threadfence();
        __syncthreads();
        if (tid == 0) atomicAdd(&g_dots_done, 1u);   // release dots
    }
    else if (bx >= 1) {
        // ========== POS blocks: float-based sign dots, no dependency =========
        const int* p32 = (const int*)pos;
        int any = 0;
        for (int i = tid; i < NP; i += NT) any |= (p32[2 * i + 1] != 0);
        const int is32 = __syncthreads_or(any);

        // 256 pairs per block, 8 per warp; lanes 0..7 fetch indices
        int p0 = (bx - 1) * 256 + warp * 8;
        int qv = 0, dv = 0;
        if (lane < 8) {
            int p = p0 + lane;
            if (is32) { qv = p32[2 * p] & (BB - 1); dv = p32[2 * p + 1] & (BB - 1); }
            else      { qv = p32[4 * p] & (BB - 1); dv = p32[4 * p + 2] & (BB - 1); }
        }
        unsigned acc = 0;
        #pragma unroll
        for (int i = 0; i < 8; ++i) {
            int q = __shfl_sync(0xffffffffu, qv, i);
            int d = __shfl_sync(0xffffffffu, dv, i);
            float4 a = ((const float4*)bh)[q * 32 + lane];
            float4 b = ((const float4*)bh)[d * 32 + lane];
            int mm = ((a.x < 0.f) != (b.x < 0.f))
                   + ((a.y < 0.f) != (b.y < 0.f))
                   + ((a.z < 0.f) != (b.z < 0.f))
                   + ((a.w < 0.f) != (b.w < 0.f));
            #pragma unroll
            for (int off = 16; off; off >>= 1)
                mm += __shfl_down_sync(0xffffffffu, mm, off);
            if (lane == 0) {
                int diff = MARGIN - (LBITS - 2 * mm);   // margin - dot
                if (diff > 0) acc += (unsigned)(diff * diff);
            }
        }
        if (lane == 0) s_q[warp] = __uint_as_float(acc);
        __syncthreads();
        if (tid == 0) {
            unsigned bs = 0;
            #pragma unroll
            for (int w = 0; w < NT / 32; ++w) bs += __float_as_uint(s_q[w]);
            g_pos_part[bx - 1] = bs;
        }
        __threadfence();
        __syncthreads();
    }
    else {
        // ========== NEG block: prep overlapped, wait only for dots ===========
        if (tid == 0) s_epoch = atomicAdd(&g_epoch, 1u);
        const int* p32 = (const int*)pos;
        int any = 0;
        for (int i = tid; i < NP; i += NT) any |= (p32[2 * i + 1] != 0);
        const int is32 = __syncthreads_or(any);

        // selection provably confined to rows 0,1: they hold
        // >= 2*(BB-1) - 2*NP = 8190 >= NP candidates.
        for (int i = tid; i < (2 * BB) / 4; i += NT) ((int*)flags)[i] = 0;
        __syncthreads();
        for (int p = tid; p < NP; p += NT) {
            int q, d;
            if (is32) { q = p32[2 * p] & (BB - 1); d = p32[2 * p + 1] & (BB - 1); }
            else      { q = p32[4 * p] & (BB - 1); d = p32[4 * p + 2] & (BB - 1); }
            if (q < 2) flags[q * BB + d] = 1;
            if (d < 2) flags[d * BB + q] = 1;
        }
        if (tid == 0) { flags[0] = 1; flags[BB + 1] = 1; }  // diag (0,0),(1,1)
        __syncthreads();

        const int base = tid * 16;
        int cnt = 0;
        #pragma unroll
        for (int i = 0; i < 16; ++i) cnt += flags[base + i] ? 0 : 1;
        scan[tid] = cnt;
        __syncthreads();
        for (int off = 1; off < NT; off <<= 1) {   // Hillis-Steele, 10 steps
            int v = (tid >= off) ? scan[tid - off] : 0;
            __syncthreads();
            scan[tid] += v;
            __syncthreads();
        }

        // wait: all pack blocks published their dots for THIS replay
        if (tid == 0) {
            unsigned target = (s_epoch + 1u) * NPACK;
            while (*(volatile unsigned*)&g_dots_done < target) { }
        }
        __syncthreads();
        __threadfence();   // acquire g_dots

        const int row  = base >> 13;
        const int col0 = base & (BB - 1);
        unsigned dw[16];
        #pragma unroll
        for (int j = 0; j < 4; ++j) {
            uint4 w = g_dots4[(col0 >> 2) + j];
            dw[4 * j + 0] = w.x; dw[4 * j + 1] = w.y;
            dw[4 * j + 2] = w.z; dw[4 * j + 3] = w.w;
        }
        int run = scan[tid] - cnt;   // exclusive prefix of candidates
        unsigned acc = 0;
        #pragma unroll
        for (int i = 0; i < 16; ++i) {
            if (!flags[base + i]) {
                if (run < NP) {
                    unsigned v = dw[i];
                    int dot = (int)(row ? (v >> 16) : (v & 0xffffu)) - 128;
                    int t = dot + MARGIN;
                    if (t > 0) acc += (unsigned)(t * t);
                }
                run++;
            }
        }
        #pragma unroll
        for (int off = 16; off; off >>= 1)
            acc += __shfl_down_sync(0xffffffffu, acc, off);
        if (lane == 0) s_q[warp] = __uint_as_float(acc);
        __syncthreads();
        if (tid == 0) {
            unsigned bs = 0;
            #pragma unroll
            for (int w = 0; w < NT / 32; ++w) bs += __float_as_uint(s_q[w]);
            g_neg_part = bs;
        }
        __threadfence();
        __syncthreads();
    }

    // ================= done ticket: globally-last block combines ==============
    if (tid == 0) {
        unsigned t2 = atomicAdd(&g_done, 1u);
        if (t2 % GRID == (GRID - 1)) s_final = 1;
    }
    __syncthreads();

    if (s_final) {
        __threadfence();   // acquire all partials
        // ---- parallel colsum reduction: 1024 threads over 128x128 ints ----
        if (tid < LBITS) s_col[tid] = 0;
        __syncthreads();
        {
            int c = tid & (LBITS - 1);
            int g = tid >> 7;            // 0..7
            int cs = 0;
            #pragma unroll
            for (int k = 0; k < NPACK / 8; ++k)
                cs += g_col_part[g * (NPACK / 8) + k][c];
            atomicAdd(&s_col[c], cs);
        }
        __syncthreads();
        if (tid < LBITS) {
            double m = (double)s_col[tid] / (double)BB;
            s_d[tid] = m * m;
        }
        __syncthreads();
        double bal = 0.0;
        if (tid == 0) {
            #pragma unroll 8
            for (int c = 0; c < LBITS; ++c) bal += s_d[c];
        }
        __syncthreads();
        if (tid < NPACK) s_d[tid] = g_quant_part[tid];   // parallel fetch
        __syncthreads();
        if (tid == 0) {
            double qs = 0.0;
            #pragma unroll 8
            for (int b = 0; b < NPACK; ++b) qs += s_d[b];
            unsigned long long psum = (unsigned long long)g_neg_part;
            #pragma unroll
            for (int b = 0; b < NPOSB; ++b) psum += g_pos_part[b];
            // num_neg = min(~67M, NP) = NP always for this shape
            double sim   = (double)psum / (double)(NP + NP);
            double quant = qs / ((double)BB * (double)LBITS);
            out[0] = (float)(sim + 0.5 * quant + 0.1 * bal);
        }
    }
}

// ---------------- launch ------------------------------------------------------
extern "C" void kernel_launch(void* const* d_in, const int* in_sizes, int n_in,
                              void* d_out, int out_size) {
    const float* bh  = (const float*)d_in[0];
    const float* ch  = (const float*)d_in[1];
    const void*  pos = (const void*)d_in[2];
    fused_kernel<<<GRID, NT>>>(bh, ch, pos, (float*)d_out);
}

// round 8
// speedup vs baseline: 2.7280x; 1.3378x over previous
#include <cuda_runtime.h>
#include <cuda_bf16.h>
#include <stdint.h>

#define BB      8192
#define LBITS   128
#define NP      4096
#define MARGIN  64
#define NPOSB   16                 // blocks 1..16: positive pairs
#define NPACK   128                // blocks 17..144: streaming/pack
#define PACK0   (1 + NPOSB)
#define GRID    (1 + NPOSB + NPACK)   // 145 blocks, single wave
#define NT      1024

// ---------------- device scratch (static, zero-init at load) -----------------
__device__ double       g_quant_part[NPACK];
__device__ int          g_col_part[NPACK][LBITS];
__device__ unsigned     g_pos_part[NPOSB];
__device__ unsigned     g_neg_part;
__device__ uint4        g_dots4[BB / 4];   // per row: (dot0+128)|(dot1+128)<<16
__device__ unsigned     g_dots_done;       // monotonic: +1 per pack block
__device__ unsigned     g_epoch;           // monotonic: neg-block replay ticket
__device__ unsigned     g_done;            // monotonic: all-blocks done ticket

__global__ void __launch_bounds__(NT, 1)
fused_kernel(const float* __restrict__ bh,
             const float* __restrict__ ch,
             const void*  __restrict__ pos,
             float*       __restrict__ out)
{
    __shared__ unsigned char flags[2 * BB];   // 16 KB (neg block only)
    __shared__ int    scan[NT / 32];          // warp totals
    __shared__ int    s_col[LBITS];
    __shared__ float  s_q[NT / 32];
    __shared__ double s_d[LBITS];
    __shared__ int    s_final;
    __shared__ unsigned s_epoch;

    const int tid  = threadIdx.x;
    const int warp = tid >> 5;
    const int lane = tid & 31;
    const int bx   = blockIdx.x;

    if (tid == 0) s_final = 0;

    if (bx >= PACK0) {
        // ========== PACK blocks: stream bh+ch, colsums, quant, dots vs r0/r1 =
        const int pb = bx - PACK0;
        if (tid < LBITS) s_col[tid] = 0;
        __syncthreads();

        // rows 0 and 1 packed bits (identical in every warp; L2 broadcast)
        float4 r0f = ((const float4*)bh)[lane];
        float4 r1f = ((const float4*)bh)[32 + lane];
        unsigned r00 = __ballot_sync(0xffffffffu, r0f.x < 0.f);
        unsigned r01 = __ballot_sync(0xffffffffu, r0f.y < 0.f);
        unsigned r02 = __ballot_sync(0xffffffffu, r0f.z < 0.f);
        unsigned r03 = __ballot_sync(0xffffffffu, r0f.w < 0.f);
        unsigned r10 = __ballot_sync(0xffffffffu, r1f.x < 0.f);
        unsigned r11 = __ballot_sync(0xffffffffu, r1f.y < 0.f);
        unsigned r12 = __ballot_sync(0xffffffffu, r1f.z < 0.f);
        unsigned r13 = __ballot_sync(0xffffffffu, r1f.w < 0.f);

        float quacc = 0.f;
        int ca0 = 0, ca1 = 0, ca2 = 0, ca3 = 0;
        #pragma unroll
        for (int it = 0; it < 2; ++it) {
            int r = pb * 64 + warp * 2 + it;       // 64 rows per block
            float4 x = ((const float4*)bh)[r * 32 + lane];
            float4 c = ((const float4*)ch)[r * 32 + lane];
            unsigned b0 = __ballot_sync(0xffffffffu, x.x < 0.f);
            unsigned b1 = __ballot_sync(0xffffffffu, x.y < 0.f);
            unsigned b2 = __ballot_sync(0xffffffffu, x.z < 0.f);
            unsigned b3 = __ballot_sync(0xffffffffu, x.w < 0.f);
            int D0 = __popc(b0 ^ r00) + __popc(b1 ^ r01)
                   + __popc(b2 ^ r02) + __popc(b3 ^ r03);
            int D1 = __popc(b0 ^ r10) + __popc(b1 ^ r11)
                   + __popc(b2 ^ r12) + __popc(b3 ^ r13);
            if (lane == 0)
                ((unsigned*)g_dots4)[r] =
                    (unsigned)(LBITS - 2 * D0 + 128)
                  | ((unsigned)(LBITS - 2 * D1 + 128) << 16);
            ca0 += (x.x < 0.f) ? -1 : 1;
            ca1 += (x.y < 0.f) ? -1 : 1;
            ca2 += (x.z < 0.f) ? -1 : 1;
            ca3 += (x.w < 0.f) ? -1 : 1;
            quacc += fabsf(fabsf(c.x) - 1.f) + fabsf(fabsf(c.y) - 1.f)
                   + fabsf(fabsf(c.z) - 1.f) + fabsf(fabsf(c.w) - 1.f);
        }
        // consistent lane->column permutation across all rows: invariant
        atomicAdd(&s_col[4 * lane + 0], ca0);
        atomicAdd(&s_col[4 * lane + 1], ca1);
        atomicAdd(&s_col[4 * lane + 2], ca2);
        atomicAdd(&s_col[4 * lane + 3], ca3);
        #pragma unroll
        for (int off = 16; off; off >>= 1)
            quacc += __shfl_down_sync(0xffffffffu, quacc, off);
        if (lane == 0) s_q[warp] = quacc;
        __syncthreads();
        if (tid < LBITS) g_col_part[pb][tid] = s_col[tid];
        if (warp == 0) {                         // shfl tree, fixed order
            float qq = s_q[lane];
            #pragma unroll
            for (int off = 16; off; off >>= 1)
                qq += __shfl_down_sync(0xffffffffu, qq, off);
            if (lane == 0) g_quant_part[pb] = (double)qq;
        }
        __threadfence();
        __syncthreads();
        if (tid == 0) atomicAdd(&g_dots_done, 1u);   // release dots
    }
    else if (bx >= 1) {
        // ========== POS blocks: float sign dots, 4 pairs per reduction =======
        const int* p32 = (const int*)pos;
        int any = 0;
        for (int i = tid; i < NP; i += NT) any |= (p32[2 * i + 1] != 0);
        const int is32 = __syncthreads_or(any);

        // 256 pairs per block, 8 per warp; lanes 0..7 fetch indices
        int p0 = (bx - 1) * 256 + warp * 8;
        int qv = 0, dv = 0;
        if (lane < 8) {
            int p = p0 + lane;
            if (is32) { qv = p32[2 * p] & (BB - 1); dv = p32[2 * p + 1] & (BB - 1); }
            else      { qv = p32[4 * p] & (BB - 1); dv = p32[4 * p + 2] & (BB - 1); }
        }
        unsigned acc = 0;
        #pragma unroll
        for (int g = 0; g < 2; ++g) {
            // gather 4 pairs' rows first (8 independent loads, front-batched)
            float4 av[4], bv[4];
            #pragma unroll
            for (int j = 0; j < 4; ++j) {
                int q = __shfl_sync(0xffffffffu, qv, 4 * g + j);
                int d = __shfl_sync(0xffffffffu, dv, 4 * g + j);
                av[j] = ((const float4*)bh)[q * 32 + lane];
                bv[j] = ((const float4*)bh)[d * 32 + lane];
            }
            unsigned packed = 0;
            #pragma unroll
            for (int j = 0; j < 4; ++j) {
                unsigned mm = ((av[j].x < 0.f) != (bv[j].x < 0.f))
                            + ((av[j].y < 0.f) != (bv[j].y < 0.f))
                            + ((av[j].z < 0.f) != (bv[j].z < 0.f))
                            + ((av[j].w < 0.f) != (bv[j].w < 0.f));
                packed |= mm << (8 * j);     // per-pair sum <= 128: no carry
            }
            #pragma unroll
            for (int off = 16; off; off >>= 1)
                packed += __shfl_down_sync(0xffffffffu, packed, off);
            if (lane == 0) {
                #pragma unroll
                for (int j = 0; j < 4; ++j) {
                    int mm = (int)((packed >> (8 * j)) & 0xffu);
                    int diff = MARGIN - (LBITS - 2 * mm);   // margin - dot
                    if (diff > 0) acc += (unsigned)(diff * diff);
                }
            }
        }
        if (lane == 0) s_q[warp] = __uint_as_float(acc);
        __syncthreads();
        if (warp == 0) {
            unsigned bs = __float_as_uint(s_q[lane]);
            #pragma unroll
            for (int off = 16; off; off >>= 1)
                bs += __shfl_down_sync(0xffffffffu, bs, off);
            if (lane == 0) g_pos_part[bx - 1] = bs;
        }
        __threadfence();
        __syncthreads();
    }
    else {
        // ========== NEG block: prep overlapped, wait only for dots ===========
        if (tid == 0) s_epoch = atomicAdd(&g_epoch, 1u);
        const int* p32 = (const int*)pos;
        int any = 0;
        for (int i = tid; i < NP; i += NT) any |= (p32[2 * i + 1] != 0);
        const int is32 = __syncthreads_or(any);

        // selection provably confined to rows 0,1: they hold
        // >= 2*(BB-1) - 2*NP = 8190 >= NP candidates.
        for (int i = tid; i < (2 * BB) / 4; i += NT) ((int*)flags)[i] = 0;
        __syncthreads();
        for (int p = tid; p < NP; p += NT) {
            int q, d;
            if (is32) { q = p32[2 * p] & (BB - 1); d = p32[2 * p + 1] & (BB - 1); }
            else      { q = p32[4 * p] & (BB - 1); d = p32[4 * p + 2] & (BB - 1); }
            if (q < 2) flags[q * BB + d] = 1;
            if (d < 2) flags[d * BB + q] = 1;
        }
        if (tid == 0) { flags[0] = 1; flags[BB + 1] = 1; }  // diag (0,0),(1,1)
        __syncthreads();

        const int base = tid * 16;
        int cnt = 0;
        #pragma unroll
        for (int i = 0; i < 16; ++i) cnt += flags[base + i] ? 0 : 1;
        // ---- shfl-based block scan (3 barriers instead of 20) ----
        int val = cnt;
        #pragma unroll
        for (int off = 1; off < 32; off <<= 1) {
            int n = __shfl_up_sync(0xffffffffu, val, off);
            if (lane >= off) val += n;
        }
        if (lane == 31) scan[warp] = val;       // warp totals
        __syncthreads();
        if (warp == 0) {
            int t = scan[lane];
            #pragma unroll
            for (int off = 1; off < 32; off <<= 1) {
                int n = __shfl_up_sync(0xffffffffu, t, off);
                if (lane >= off) t += n;
            }
            scan[lane] = t;                     // inclusive warp-total prefix
        }
        __syncthreads();
        int run = ((warp == 0) ? 0 : scan[warp - 1]) + val - cnt;  // exclusive

        // wait: all pack blocks published their dots for THIS replay
        if (tid == 0) {
            unsigned target = (s_epoch + 1u) * NPACK;
            while (*(volatile unsigned*)&g_dots_done < target) { }
        }
        __syncthreads();
        __threadfence();   // acquire g_dots

        const int row  = base >> 13;
        const int col0 = base & (BB - 1);
        unsigned dw[16];
        #pragma unroll
        for (int j = 0; j < 4; ++j) {
            uint4 w = g_dots4[(col0 >> 2) + j];
            dw[4 * j + 0] = w.x; dw[4 * j + 1] = w.y;
            dw[4 * j + 2] = w.z; dw[4 * j + 3] = w.w;
        }
        unsigned acc = 0;
        #pragma unroll
        for (int i = 0; i < 16; ++i) {
            if (!flags[base + i]) {
                if (run < NP) {
                    unsigned v = dw[i];
                    int dot = (int)(row ? (v >> 16) : (v & 0xffffu)) - 128;
                    int t = dot + MARGIN;
                    if (t > 0) acc += (unsigned)(t * t);
                }
                run++;
            }
        }
        #pragma unroll
        for (int off = 16; off; off >>= 1)
            acc += __shfl_down_sync(0xffffffffu, acc, off);
        if (lane == 0) s_q[warp] = __uint_as_float(acc);
        __syncthreads();
        if (warp == 0) {
            unsigned bs = __float_as_uint(s_q[lane]);
            #pragma unroll
            for (int off = 16; off; off >>= 1)
                bs += __shfl_down_sync(0xffffffffu, bs, off);
            if (lane == 0) g_neg_part = bs;
        }
        __threadfence();
        __syncthreads();
    }

    // ================= done ticket: globally-last block combines ==============
    if (tid == 0) {
        unsigned t2 = atomicAdd(&g_done, 1u);
        if (t2 % GRID == (GRID - 1)) s_final = 1;
    }
    __syncthreads();

    if (s_final) {
        __threadfence();   // acquire all partials
        // ---- parallel colsum reduction: 1024 threads over 128x128 ints ----
        if (tid < LBITS) s_col[tid] = 0;
        __syncthreads();
        {
            int c = tid & (LBITS - 1);
            int g = tid >> 7;            // 0..7
            int cs = 0;
            #pragma unroll
            for (int k = 0; k < NPACK / 8; ++k)
                cs += g_col_part[g * (NPACK / 8) + k][c];
            atomicAdd(&s_col[c], cs);
        }
        __syncthreads();
        if (tid < LBITS) {
            double m = (double)s_col[tid] / (double)BB;
            s_d[tid] = m * m;
        }
        __syncthreads();
        // tree-reduce bal (7 steps; no serial 128-DADD chain)
        #pragma unroll
        for (int off = 64; off > 0; off >>= 1) {
            if (tid < off) s_d[tid] += s_d[tid + off];
            __syncthreads();
        }
        double bal = s_d[0];               // valid in thread 0
        __syncthreads();
        if (tid < NPACK) s_d[tid] = g_quant_part[tid];
        __syncthreads();
        #pragma unroll
        for (int off = 64; off > 0; off >>= 1) {
            if (tid < off) s_d[tid] += s_d[tid + off];
            __syncthreads();
        }
        if (tid == 0) {
            double qs = s_d[0];
            unsigned long long psum = (unsigned long long)g_neg_part;
            #pragma unroll
            for (int b = 0; b < NPOSB; ++b) psum += g_pos_part[b];
            // num_neg = min(~67M, NP) = NP always for this shape
            double sim   = (double)psum / (double)(NP + NP);
            double quant = qs / ((double)BB * (double)LBITS);
            out[0] = (float)(sim + 0.5 * quant + 0.1 * bal);
        }
    }
}

// ---------------- launch ------------------------------------------------------
extern "C" void kernel_launch(void* const* d_in, const int* in_sizes, int n_in,
                              void* d_out, int out_size) {
    const float* bh  = (const float*)d_in[0];
    const float* ch  = (const float*)d_in[1];
    const void*  pos = (const void*)d_in[2];
    fused_kernel<<<GRID, NT>>>(bh, ch, pos, (float*)d_out);
}